// round 2
// baseline (speedup 1.0000x reference)
#include <cuda_runtime.h>

// Problem constants (fixed shapes from the reference)
#define Bc      128
#define Sc      37        // sensors
#define Tc      2048      // time steps
#define Dc      256       // d_model
#define STc     8         // static dims
#define Cc      2         // classes
#define Fc      (2 * Sc)  // 74 features (x ++ mask)
#define MERGEDc (Dc + STc) // 264
#define NTHR    256

__global__ __launch_bounds__(NTHR, 1)
void fused_encoder_classifier(const float* __restrict__ x,        // [B,S,T]
                              const float* __restrict__ stat_in,  // [B,ST]
                              const float* __restrict__ time_in,  // [B,T]
                              const int*   __restrict__ smask,    // [B,S,T]
                              const float* __restrict__ W_sensor, // [2S,D]
                              const float* __restrict__ b_sensor, // [D]
                              const float* __restrict__ W_time,   // [1,D]
                              const float* __restrict__ b_time,   // [D]
                              const float* __restrict__ W_static, // [ST,ST]
                              const float* __restrict__ b_static, // [ST]
                              const float* __restrict__ W_merge,  // [MERGED,MERGED]
                              const float* __restrict__ b_merge,  // [MERGED]
                              const float* __restrict__ W_cls,    // [MERGED,C]
                              const float* __restrict__ b_cls,    // [C]
                              float* __restrict__ out)            // [B,C]
{
    const int b    = blockIdx.x;
    const int tid  = threadIdx.x;
    const int lane = tid & 31;
    const int warp = tid >> 5;

    const float* xb = x     + (size_t)b * Sc * Tc;
    const int*   mb = smask + (size_t)b * Sc * Tc;
    const float* tb = time_in + (size_t)b * Tc;

    // ---- Phase 1: masked streaming reduction over T (the only DRAM-heavy part)
    // pooled numerators: sum_t m * x[b,s,t]  (features 0..36)
    //                    sum_t m * mask[b,s,t] (features 37..73, mask values are 0/1)
    float accx[Sc];
    float accm[Sc];
#pragma unroll
    for (int s = 0; s < Sc; ++s) { accx[s] = 0.f; accm[s] = 0.f; }
    float tsum  = 0.f;  // sum_t m * time[b,t]
    float denom = 0.f;  // sum_t m

    for (int t = tid; t < Tc; t += NTHR) {
        float xv[Sc];
        unsigned long long bits = 0ull;
        bool any = false;
#pragma unroll
        for (int s = 0; s < Sc; ++s) {
            xv[s] = __ldg(&xb[s * Tc + t]);
            int mv = __ldg(&mb[s * Tc + t]);
            bits |= ((unsigned long long)(mv != 0)) << s;
            any |= (xv[s] != 0.f);
        }
        any |= (bits != 0ull);
        if (any) {  // m == 1 exactly
#pragma unroll
            for (int s = 0; s < Sc; ++s) {
                accx[s] += xv[s];
                accm[s] += (float)((bits >> s) & 1ull);
            }
            tsum  += __ldg(&tb[t]);
            denom += 1.f;
        }
    }

    // ---- warp-level butterfly reduction of 76 accumulators
#pragma unroll
    for (int s = 0; s < Sc; ++s) {
#pragma unroll
        for (int o = 16; o > 0; o >>= 1) {
            accx[s] += __shfl_xor_sync(0xFFFFFFFFu, accx[s], o);
            accm[s] += __shfl_xor_sync(0xFFFFFFFFu, accm[s], o);
        }
    }
#pragma unroll
    for (int o = 16; o > 0; o >>= 1) {
        tsum  += __shfl_xor_sync(0xFFFFFFFFu, tsum,  o);
        denom += __shfl_xor_sync(0xFFFFFFFFu, denom, o);
    }

    __shared__ float red[NTHR / 32][Fc + 2];  // 8 x 76
    if (lane == 0) {
#pragma unroll
        for (int s = 0; s < Sc; ++s) {
            red[warp][s]      = accx[s];
            red[warp][Sc + s] = accm[s];
        }
        red[warp][Fc]     = tsum;
        red[warp][Fc + 1] = denom;
    }
    __syncthreads();

    __shared__ float sx[Fc + 2];  // [0..73] pooled feature sums, [74]=tsum, [75]=denom
    if (tid < Fc + 2) {
        float v = 0.f;
#pragma unroll
        for (int w = 0; w < NTHR / 32; ++w) v += red[w][tid];
        sx[tid] = v;
    }
    __syncthreads();

    // ---- Phase 2: tiny MLP head, all weights L2-resident
    __shared__ float comb[MERGEDc];
    const float denomR = sx[Fc + 1];
    const float denomC = fmaxf(denomR, 1e-9f);
    const float tsumR  = sx[Fc];

    // pooled[d] via factored projection; one thread per d (tid == d, 256 threads)
    {
        const int d = tid;
        float a0 = 0.f, a1 = 0.f;
#pragma unroll
        for (int f = 0; f < Fc; f += 2) {
            a0 += sx[f]     * __ldg(&W_sensor[f * Dc + d]);
            a1 += sx[f + 1] * __ldg(&W_sensor[(f + 1) * Dc + d]);
        }
        float acc = a0 + a1
                  + tsumR  * __ldg(&W_time[d])
                  + denomR * (__ldg(&b_sensor[d]) + __ldg(&b_time[d]));
        comb[d] = acc / denomC;
    }
    // static embedding: comb[256..263]
    if (tid < STc) {
        float a = __ldg(&b_static[tid]);
#pragma unroll
        for (int i = 0; i < STc; ++i)
            a += __ldg(&stat_in[b * STc + i]) * __ldg(&W_static[i * STc + tid]);
        comb[Dc + tid] = a;
    }
    __syncthreads();

    // merge layer + ReLU: combr[j] = relu(b_merge[j] + sum_i comb[i] * W_merge[i,j])
    __shared__ float combr[MERGEDc];
    for (int j = tid; j < MERGEDc; j += NTHR) {
        float a0 = 0.f, a1 = 0.f, a2 = 0.f, a3 = 0.f;
#pragma unroll 4
        for (int i = 0; i < MERGEDc; i += 4) {  // 264 = 4*66
            a0 += comb[i]     * __ldg(&W_merge[(i)     * MERGEDc + j]);
            a1 += comb[i + 1] * __ldg(&W_merge[(i + 1) * MERGEDc + j]);
            a2 += comb[i + 2] * __ldg(&W_merge[(i + 2) * MERGEDc + j]);
            a3 += comb[i + 3] * __ldg(&W_merge[(i + 3) * MERGEDc + j]);
        }
        float a = __ldg(&b_merge[j]) + ((a0 + a1) + (a2 + a3));
        combr[j] = fmaxf(a, 0.f);
    }
    __syncthreads();

    // classifier: out[b,c] = b_cls[c] + sum_i combr[i] * W_cls[i,c]
    if (warp == 0) {
        float c0 = 0.f, c1 = 0.f;
        for (int i = lane; i < MERGEDc; i += 32) {
            float v = combr[i];
            c0 += v * __ldg(&W_cls[i * Cc + 0]);
            c1 += v * __ldg(&W_cls[i * Cc + 1]);
        }
#pragma unroll
        for (int o = 16; o > 0; o >>= 1) {
            c0 += __shfl_xor_sync(0xFFFFFFFFu, c0, o);
            c1 += __shfl_xor_sync(0xFFFFFFFFu, c1, o);
        }
        if (lane == 0) {
            out[b * Cc + 0] = c0 + __ldg(&b_cls[0]);
            out[b * Cc + 1] = c1 + __ldg(&b_cls[1]);
        }
    }
}

extern "C" void kernel_launch(void* const* d_in, const int* in_sizes, int n_in,
                              void* d_out, int out_size)
{
    const float* x        = (const float*)d_in[0];
    const float* stat_in  = (const float*)d_in[1];
    const float* time_in  = (const float*)d_in[2];
    const int*   smask    = (const int*)  d_in[3];
    const float* W_sensor = (const float*)d_in[4];
    const float* b_sensor = (const float*)d_in[5];
    const float* W_time   = (const float*)d_in[6];
    const float* b_time   = (const float*)d_in[7];
    const float* W_static = (const float*)d_in[8];
    const float* b_static = (const float*)d_in[9];
    const float* W_merge  = (const float*)d_in[10];
    const float* b_merge  = (const float*)d_in[11];
    const float* W_cls    = (const float*)d_in[12];
    const float* b_cls    = (const float*)d_in[13];
    float* out = (float*)d_out;

    fused_encoder_classifier<<<Bc, NTHR>>>(x, stat_in, time_in, smask,
                                           W_sensor, b_sensor, W_time, b_time,
                                           W_static, b_static, W_merge, b_merge,
                                           W_cls, b_cls, out);
}

// round 3
// speedup vs baseline: 1.6494x; 1.6494x over previous
#include <cuda_runtime.h>

#define Bc      128
#define Sc      37
#define Tc      2048
#define Dc      256
#define STc     8
#define Cc      2
#define Fc      (2 * Sc)        // 74
#define MERGEDc (Dc + STc)      // 264
#define SPLIT   4
#define CHUNK   (Tc / SPLIT)    // 512 t per CTA
#define NT1     128
#define W1      (NT1 / 32)      // 4 warps
#define NPART   (SPLIT * W1)    // 16 partials per batch
#define NT2     256

// Per-batch partial sums: [0..36]=sum x, [37..73]=sum mask, [74]=sum valid*time, [75]=sum valid
__device__ float g_part[Bc][NPART][80];

// ---------------------------------------------------------------------------
// Phase 1: unconditional streaming sums over T (DRAM-bound part)
// ---------------------------------------------------------------------------
__global__ __launch_bounds__(NT1, 4)
void phase1(const float* __restrict__ x,        // [B,S,T]
            const int*   __restrict__ smask,    // [B,S,T]
            const float* __restrict__ time_in)  // [B,T]
{
    const int blk  = blockIdx.x;
    const int b    = blk >> 2;          // / SPLIT
    const int part = blk & (SPLIT - 1);
    const int tid  = threadIdx.x;
    const int lane = tid & 31;
    const int warp = tid >> 5;
    const int t0   = part * CHUNK + tid * 4;   // this thread's 4 time steps

    const float4* xb = (const float4*)(x     + (size_t)b * Sc * Tc);
    const int4*   mb = (const int4*)  (smask + (size_t)b * Sc * Tc);

    float psum[Sc];
    int   pm[Sc];
    int v0 = 0, v1 = 0, v2 = 0, v3 = 0;   // per-t validity flags

#pragma unroll
    for (int s = 0; s < Sc; ++s) {
        const int idx = (s * Tc + t0) >> 2;
        float4 xv = __ldg(&xb[idx]);
        int4   mv = __ldg(&mb[idx]);
        // valid[t]=0 => every feature at t is 0, so plain sums equal masked sums
        psum[s] = (xv.x + xv.y) + (xv.z + xv.w);
        pm[s]   = (mv.x + mv.y) + (mv.z + mv.w);
        v0 |= (int)((xv.x != 0.f) | (mv.x != 0));
        v1 |= (int)((xv.y != 0.f) | (mv.y != 0));
        v2 |= (int)((xv.z != 0.f) | (mv.z != 0));
        v3 |= (int)((xv.w != 0.f) | (mv.w != 0));
    }

    float4 tv = __ldg((const float4*)(time_in + (size_t)b * Tc) + (t0 >> 2));
    float tsum = (float)v0 * tv.x + (float)v1 * tv.y
               + (float)v2 * tv.z + (float)v3 * tv.w;
    float den  = (float)(v0 + v1 + v2 + v3);

    // ---- butterfly reduce the 76 per-thread values within each warp
#pragma unroll
    for (int s = 0; s < Sc; ++s) {
#pragma unroll
        for (int o = 16; o > 0; o >>= 1) {
            psum[s] += __shfl_xor_sync(0xFFFFFFFFu, psum[s], o);
            pm[s]   += __shfl_xor_sync(0xFFFFFFFFu, pm[s],   o);
        }
    }
#pragma unroll
    for (int o = 16; o > 0; o >>= 1) {
        tsum += __shfl_xor_sync(0xFFFFFFFFu, tsum, o);
        den  += __shfl_xor_sync(0xFFFFFFFFu, den,  o);
    }

    // ---- per-warp partial -> shared -> coalesced store to global scratch
    __shared__ float st[W1][80];
    if (lane == 0) {
#pragma unroll
        for (int s = 0; s < Sc; ++s) {
            st[warp][s]      = psum[s];
            st[warp][Sc + s] = (float)pm[s];
        }
        st[warp][Fc]     = tsum;
        st[warp][Fc + 1] = den;
    }
    __syncthreads();

    for (int i = tid; i < W1 * 76; i += NT1) {
        int w = i / 76, f = i % 76;
        g_part[b][part * W1 + w][f] = st[w][f];
    }
}

// ---------------------------------------------------------------------------
// Phase 2: combine partials + tiny MLP head (weights L2-resident)
// ---------------------------------------------------------------------------
__global__ __launch_bounds__(NT2, 1)
void phase2(const float* __restrict__ stat_in,  // [B,ST]
            const float* __restrict__ W_sensor, // [2S,D]
            const float* __restrict__ b_sensor, // [D]
            const float* __restrict__ W_time,   // [1,D]
            const float* __restrict__ b_time,   // [D]
            const float* __restrict__ W_static, // [ST,ST]
            const float* __restrict__ b_static, // [ST]
            const float* __restrict__ W_merge,  // [MERGED,MERGED]
            const float* __restrict__ b_merge,  // [MERGED]
            const float* __restrict__ W_cls,    // [MERGED,C]
            const float* __restrict__ b_cls,    // [C]
            float* __restrict__ out)            // [B,C]
{
    const int b    = blockIdx.x;
    const int tid  = threadIdx.x;
    const int lane = tid & 31;
    const int warp = tid >> 5;

    __shared__ float sx[76];   // [0..73] pooled feature sums, [74]=tsum, [75]=denom
    if (tid < 76) {
        float acc = 0.f;
#pragma unroll
        for (int p = 0; p < NPART; ++p) acc += g_part[b][p][tid];
        sx[tid] = acc;
    }
    __syncthreads();

    __shared__ float comb[MERGEDc];
    const float denomR = sx[Fc + 1];
    const float denomC = fmaxf(denomR, 1e-9f);
    const float tsumR  = sx[Fc];

    // pooled[d] via factored projection; one thread per d
    {
        const int d = tid;
        float a0 = 0.f, a1 = 0.f;
#pragma unroll
        for (int f = 0; f < Fc; f += 2) {
            a0 += sx[f]     * __ldg(&W_sensor[f * Dc + d]);
            a1 += sx[f + 1] * __ldg(&W_sensor[(f + 1) * Dc + d]);
        }
        float acc = a0 + a1
                  + tsumR  * __ldg(&W_time[d])
                  + denomR * (__ldg(&b_sensor[d]) + __ldg(&b_time[d]));
        comb[d] = acc / denomC;
    }
    if (tid < STc) {
        float a = __ldg(&b_static[tid]);
#pragma unroll
        for (int i = 0; i < STc; ++i)
            a += __ldg(&stat_in[b * STc + i]) * __ldg(&W_static[i * STc + tid]);
        comb[Dc + tid] = a;
    }
    __syncthreads();

    __shared__ float combr[MERGEDc];
    for (int j = tid; j < MERGEDc; j += NT2) {
        float a0 = 0.f, a1 = 0.f, a2 = 0.f, a3 = 0.f;
#pragma unroll 4
        for (int i = 0; i < MERGEDc; i += 4) {   // 264 = 4*66
            a0 += comb[i]     * __ldg(&W_merge[(i)     * MERGEDc + j]);
            a1 += comb[i + 1] * __ldg(&W_merge[(i + 1) * MERGEDc + j]);
            a2 += comb[i + 2] * __ldg(&W_merge[(i + 2) * MERGEDc + j]);
            a3 += comb[i + 3] * __ldg(&W_merge[(i + 3) * MERGEDc + j]);
        }
        float a = __ldg(&b_merge[j]) + ((a0 + a1) + (a2 + a3));
        combr[j] = fmaxf(a, 0.f);
    }
    __syncthreads();

    if (warp == 0) {
        float c0 = 0.f, c1 = 0.f;
        for (int i = lane; i < MERGEDc; i += 32) {
            float v = combr[i];
            c0 += v * __ldg(&W_cls[i * Cc + 0]);
            c1 += v * __ldg(&W_cls[i * Cc + 1]);
        }
#pragma unroll
        for (int o = 16; o > 0; o >>= 1) {
            c0 += __shfl_xor_sync(0xFFFFFFFFu, c0, o);
            c1 += __shfl_xor_sync(0xFFFFFFFFu, c1, o);
        }
        if (lane == 0) {
            out[b * Cc + 0] = c0 + __ldg(&b_cls[0]);
            out[b * Cc + 1] = c1 + __ldg(&b_cls[1]);
        }
    }
}

extern "C" void kernel_launch(void* const* d_in, const int* in_sizes, int n_in,
                              void* d_out, int out_size)
{
    const float* x        = (const float*)d_in[0];
    const float* stat_in  = (const float*)d_in[1];
    const float* time_in  = (const float*)d_in[2];
    const int*   smask    = (const int*)  d_in[3];
    const float* W_sensor = (const float*)d_in[4];
    const float* b_sensor = (const float*)d_in[5];
    const float* W_time   = (const float*)d_in[6];
    const float* b_time   = (const float*)d_in[7];
    const float* W_static = (const float*)d_in[8];
    const float* b_static = (const float*)d_in[9];
    const float* W_merge  = (const float*)d_in[10];
    const float* b_merge  = (const float*)d_in[11];
    const float* W_cls    = (const float*)d_in[12];
    const float* b_cls    = (const float*)d_in[13];
    float* out = (float*)d_out;

    phase1<<<Bc * SPLIT, NT1>>>(x, smask, time_in);
    phase2<<<Bc, NT2>>>(stat_in, W_sensor, b_sensor, W_time, b_time,
                        W_static, b_static, W_merge, b_merge,
                        W_cls, b_cls, out);
}

// round 4
// speedup vs baseline: 1.9623x; 1.1898x over previous
#include <cuda_runtime.h>

#define Bc      128
#define Sc      37
#define Tc      2048
#define Dc      256
#define STc     8
#define Cc      2
#define Fc      (2 * Sc)        // 74
#define MERGEDc (Dc + STc)      // 264
#define SPLIT   4
#define CHUNK   (Tc / SPLIT)    // 512 t per CTA
#define NT1     128
#define W1      (NT1 / 32)      // 4 warps
#define NPART   (SPLIT * W1)    // 16 partials per batch
#define NT2     1024
#define ICHUNK  (MERGEDc / 4)   // 66

// Per-batch partial sums: [0..36]=sum x, [37..73]=sum mask, [74]=sum valid*time, [75]=sum valid
__device__ float g_part[Bc][NPART][80];

// ---------------------------------------------------------------------------
// Phase 1: unconditional streaming sums over T (DRAM-bound part) — unchanged
// ---------------------------------------------------------------------------
__global__ __launch_bounds__(NT1, 4)
void phase1(const float* __restrict__ x,        // [B,S,T]
            const int*   __restrict__ smask,    // [B,S,T]
            const float* __restrict__ time_in)  // [B,T]
{
    const int blk  = blockIdx.x;
    const int b    = blk >> 2;
    const int part = blk & (SPLIT - 1);
    const int tid  = threadIdx.x;
    const int lane = tid & 31;
    const int warp = tid >> 5;
    const int t0   = part * CHUNK + tid * 4;

    const float4* xb = (const float4*)(x     + (size_t)b * Sc * Tc);
    const int4*   mb = (const int4*)  (smask + (size_t)b * Sc * Tc);

    float psum[Sc];
    int   pm[Sc];
    int v0 = 0, v1 = 0, v2 = 0, v3 = 0;

#pragma unroll
    for (int s = 0; s < Sc; ++s) {
        const int idx = (s * Tc + t0) >> 2;
        float4 xv = __ldg(&xb[idx]);
        int4   mv = __ldg(&mb[idx]);
        psum[s] = (xv.x + xv.y) + (xv.z + xv.w);
        pm[s]   = (mv.x + mv.y) + (mv.z + mv.w);
        v0 |= (int)((xv.x != 0.f) | (mv.x != 0));
        v1 |= (int)((xv.y != 0.f) | (mv.y != 0));
        v2 |= (int)((xv.z != 0.f) | (mv.z != 0));
        v3 |= (int)((xv.w != 0.f) | (mv.w != 0));
    }

    float4 tv = __ldg((const float4*)(time_in + (size_t)b * Tc) + (t0 >> 2));
    float tsum = (float)v0 * tv.x + (float)v1 * tv.y
               + (float)v2 * tv.z + (float)v3 * tv.w;
    float den  = (float)(v0 + v1 + v2 + v3);

#pragma unroll
    for (int s = 0; s < Sc; ++s) {
#pragma unroll
        for (int o = 16; o > 0; o >>= 1) {
            psum[s] += __shfl_xor_sync(0xFFFFFFFFu, psum[s], o);
            pm[s]   += __shfl_xor_sync(0xFFFFFFFFu, pm[s],   o);
        }
    }
#pragma unroll
    for (int o = 16; o > 0; o >>= 1) {
        tsum += __shfl_xor_sync(0xFFFFFFFFu, tsum, o);
        den  += __shfl_xor_sync(0xFFFFFFFFu, den,  o);
    }

    __shared__ float st[W1][80];
    if (lane == 0) {
#pragma unroll
        for (int s = 0; s < Sc; ++s) {
            st[warp][s]      = psum[s];
            st[warp][Sc + s] = (float)pm[s];
        }
        st[warp][Fc]     = tsum;
        st[warp][Fc + 1] = den;
    }
    __syncthreads();

    for (int i = tid; i < W1 * 76; i += NT1) {
        int w = i / 76, f = i % 76;
        g_part[b][part * W1 + w][f] = st[w][f];
    }
}

// ---------------------------------------------------------------------------
// Phase 2: combine partials + MLP head, latency-parallelized (1024 threads)
// ---------------------------------------------------------------------------
__global__ __launch_bounds__(NT2, 1)
void phase2(const float* __restrict__ stat_in,  // [B,ST]
            const float* __restrict__ W_sensor, // [2S,D]
            const float* __restrict__ b_sensor, // [D]
            const float* __restrict__ W_time,   // [1,D]
            const float* __restrict__ b_time,   // [D]
            const float* __restrict__ W_static, // [ST,ST]
            const float* __restrict__ b_static, // [ST]
            const float* __restrict__ W_merge,  // [MERGED,MERGED]
            const float* __restrict__ b_merge,  // [MERGED]
            const float* __restrict__ W_cls,    // [MERGED,C]
            const float* __restrict__ b_cls,    // [C]
            float* __restrict__ out)            // [B,C]
{
    const int b    = blockIdx.x;
    const int tid  = threadIdx.x;
    const int lane = tid & 31;
    const int g    = tid >> 8;      // 0..3  (i-split group)
    const int r    = tid & 255;     // 0..255 (output index within group)

    __shared__ float sx[76];        // pooled feature sums, [74]=tsum, [75]=denom
    __shared__ float comb[MERGEDc];
    __shared__ float combr[MERGEDc];
    __shared__ float sens_part[2][Dc];
    __shared__ float merge_part[4][MERGEDc];

    // ---- combine the 16 partials (parallel over feature x partial)
    if (tid < 76 * NPART) {
        // 1216 threads needed; we have 1024 -> two strided passes via atomic-free split
    }
    if (tid < 76) {
        float acc = 0.f;
#pragma unroll
        for (int p = 0; p < NPART; ++p) acc += g_part[b][p][tid];
        sx[tid] = acc;
    }
    __syncthreads();

    const float denomR = sx[Fc + 1];
    const float denomC = fmaxf(denomR, 1e-9f);
    const float tsumR  = sx[Fc];

    // ---- sensor projection, split f-range over 2 groups of 512 threads
    if (tid < 512) {
        const int gg = tid >> 8;          // 0 or 1
        const int d  = tid & 255;
        const int f0 = gg * 37;
        float a0 = 0.f, a1 = 0.f;
        // 37 = 18*2 + 1
#pragma unroll
        for (int k = 0; k < 36; k += 2) {
            a0 += sx[f0 + k]     * __ldg(&W_sensor[(f0 + k)     * Dc + d]);
            a1 += sx[f0 + k + 1] * __ldg(&W_sensor[(f0 + k + 1) * Dc + d]);
        }
        a0 += sx[f0 + 36] * __ldg(&W_sensor[(f0 + 36) * Dc + d]);
        sens_part[gg][d] = a0 + a1;
    }
    // static embedding
    if (tid >= 512 && tid < 512 + STc) {
        const int j = tid - 512;
        float a = __ldg(&b_static[j]);
#pragma unroll
        for (int i = 0; i < STc; ++i)
            a += __ldg(&stat_in[b * STc + i]) * __ldg(&W_static[i * STc + j]);
        comb[Dc + j] = a;
    }
    __syncthreads();

    if (tid < Dc) {
        const int d = tid;
        float acc = sens_part[0][d] + sens_part[1][d]
                  + tsumR  * __ldg(&W_time[d])
                  + denomR * (__ldg(&b_sensor[d]) + __ldg(&b_time[d]));
        comb[d] = acc / denomC;
    }
    __syncthreads();

    // ---- merge layer: 4-way split over i, thread (g, r) does i in [g*66, g*66+66)
    {
        const int i0 = g * ICHUNK;
        // main outputs j = r (0..255)
        {
            const int j = r;
            float a0 = 0.f, a1 = 0.f;
#pragma unroll
            for (int k = 0; k < ICHUNK; k += 2) {   // 66 = 2*33
                a0 += comb[i0 + k]     * __ldg(&W_merge[(i0 + k)     * MERGEDc + j]);
                a1 += comb[i0 + k + 1] * __ldg(&W_merge[(i0 + k + 1) * MERGEDc + j]);
            }
            merge_part[g][j] = a0 + a1;
        }
        // tail outputs j = 256..263 handled by r < 8
        if (r < 8) {
            const int j = Dc + r;
            float a0 = 0.f, a1 = 0.f;
#pragma unroll
            for (int k = 0; k < ICHUNK; k += 2) {
                a0 += comb[i0 + k]     * __ldg(&W_merge[(i0 + k)     * MERGEDc + j]);
                a1 += comb[i0 + k + 1] * __ldg(&W_merge[(i0 + k + 1) * MERGEDc + j]);
            }
            merge_part[g][j] = a0 + a1;
        }
    }
    __syncthreads();

    if (tid < MERGEDc) {
        const int j = tid;
        float a = __ldg(&b_merge[j])
                + ((merge_part[0][j] + merge_part[1][j])
                 + (merge_part[2][j] + merge_part[3][j]));
        combr[j] = fmaxf(a, 0.f);
    }
    __syncthreads();

    // ---- classifier (warp 0)
    if (tid < 32) {
        float c0 = 0.f, c1 = 0.f;
        for (int i = lane; i < MERGEDc; i += 32) {
            float v = combr[i];
            c0 += v * __ldg(&W_cls[i * Cc + 0]);
            c1 += v * __ldg(&W_cls[i * Cc + 1]);
        }
#pragma unroll
        for (int o = 16; o > 0; o >>= 1) {
            c0 += __shfl_xor_sync(0xFFFFFFFFu, c0, o);
            c1 += __shfl_xor_sync(0xFFFFFFFFu, c1, o);
        }
        if (lane == 0) {
            out[b * Cc + 0] = c0 + __ldg(&b_cls[0]);
            out[b * Cc + 1] = c1 + __ldg(&b_cls[1]);
        }
    }
}

extern "C" void kernel_launch(void* const* d_in, const int* in_sizes, int n_in,
                              void* d_out, int out_size)
{
    const float* x        = (const float*)d_in[0];
    const float* stat_in  = (const float*)d_in[1];
    const float* time_in  = (const float*)d_in[2];
    const int*   smask    = (const int*)  d_in[3];
    const float* W_sensor = (const float*)d_in[4];
    const float* b_sensor = (const float*)d_in[5];
    const float* W_time   = (const float*)d_in[6];
    const float* b_time   = (const float*)d_in[7];
    const float* W_static = (const float*)d_in[8];
    const float* b_static = (const float*)d_in[9];
    const float* W_merge  = (const float*)d_in[10];
    const float* b_merge  = (const float*)d_in[11];
    const float* W_cls    = (const float*)d_in[12];
    const float* b_cls    = (const float*)d_in[13];
    float* out = (float*)d_out;

    phase1<<<Bc * SPLIT, NT1>>>(x, smask, time_in);
    phase2<<<Bc, NT2>>>(stat_in, W_sensor, b_sensor, W_time, b_time,
                        W_static, b_static, W_merge, b_merge,
                        W_cls, b_cls, out);
}

// round 6
// speedup vs baseline: 2.2047x; 1.1235x over previous
#include <cuda_runtime.h>

#define Bc      128
#define Sc      37
#define Tc      2048
#define Dc      256
#define STc     8
#define Cc      2
#define Fc      (2 * Sc)        // 74
#define MERGEDc (Dc + STc)      // 264
#define SPLIT   4
#define CHUNK   (Tc / SPLIT)    // 512 t per CTA
#define NT1     128
#define W1      (NT1 / 32)      // 4 warps
#define NT2     1024
#define NG      15              // reduction groups in phase2

// Per-batch partial sums, one row per phase1 CTA:
// [0..36]=sum x, [37..73]=sum mask, [74]=sum valid*time, [75]=sum valid
__device__ float g_part[Bc][SPLIT][80];

// ---------------------------------------------------------------------------
// Phase 1: unconditional streaming sums over T (DRAM-bound, near roofline)
// ---------------------------------------------------------------------------
__global__ __launch_bounds__(NT1, 4)
void phase1(const float* __restrict__ x,        // [B,S,T]
            const int*   __restrict__ smask,    // [B,S,T]
            const float* __restrict__ time_in)  // [B,T]
{
    const int blk  = blockIdx.x;
    const int b    = blk >> 2;
    const int part = blk & (SPLIT - 1);
    const int tid  = threadIdx.x;
    const int lane = tid & 31;
    const int warp = tid >> 5;
    const int t0   = part * CHUNK + tid * 4;

    const float4* xb = (const float4*)(x     + (size_t)b * Sc * Tc);
    const int4*   mb = (const int4*)  (smask + (size_t)b * Sc * Tc);

    float psum[Sc];
    int   pm[Sc];
    int v0 = 0, v1 = 0, v2 = 0, v3 = 0;

#pragma unroll
    for (int s = 0; s < Sc; ++s) {
        const int idx = (s * Tc + t0) >> 2;
        float4 xv = __ldg(&xb[idx]);
        int4   mv = __ldg(&mb[idx]);
        // valid[t]==0 => every feature at t is 0 => plain sums == masked sums
        psum[s] = (xv.x + xv.y) + (xv.z + xv.w);
        pm[s]   = (mv.x + mv.y) + (mv.z + mv.w);
        v0 |= (int)((xv.x != 0.f) | (mv.x != 0));
        v1 |= (int)((xv.y != 0.f) | (mv.y != 0));
        v2 |= (int)((xv.z != 0.f) | (mv.z != 0));
        v3 |= (int)((xv.w != 0.f) | (mv.w != 0));
    }

    float4 tv = __ldg((const float4*)(time_in + (size_t)b * Tc) + (t0 >> 2));
    float tsum = (float)v0 * tv.x + (float)v1 * tv.y
               + (float)v2 * tv.z + (float)v3 * tv.w;
    float den  = (float)(v0 + v1 + v2 + v3);

#pragma unroll
    for (int s = 0; s < Sc; ++s) {
#pragma unroll
        for (int o = 16; o > 0; o >>= 1) {
            psum[s] += __shfl_xor_sync(0xFFFFFFFFu, psum[s], o);
            pm[s]   += __shfl_xor_sync(0xFFFFFFFFu, pm[s],   o);
        }
    }
#pragma unroll
    for (int o = 16; o > 0; o >>= 1) {
        tsum += __shfl_xor_sync(0xFFFFFFFFu, tsum, o);
        den  += __shfl_xor_sync(0xFFFFFFFFu, den,  o);
    }

    __shared__ float st[W1][80];
    if (lane == 0) {
#pragma unroll
        for (int s = 0; s < Sc; ++s) {
            st[warp][s]      = psum[s];
            st[warp][Sc + s] = (float)pm[s];
        }
        st[warp][Fc]     = tsum;
        st[warp][Fc + 1] = den;
    }
    __syncthreads();

    // collapse the 4 warp-partials here; one 76-float row per CTA to global
    if (tid < 76) {
        g_part[b][part][tid] = (st[0][tid] + st[1][tid])
                             + (st[2][tid] + st[3][tid]);
    }
}

// ---------------------------------------------------------------------------
// Phase 2: MLP head, float4-vectorized, wide reduction splits (1024 thr)
// ---------------------------------------------------------------------------
__global__ __launch_bounds__(NT2, 1)
void phase2(const float* __restrict__ stat_in,  // [B,ST]
            const float* __restrict__ W_sensor, // [2S,D]
            const float* __restrict__ b_sensor, // [D]
            const float* __restrict__ W_time,   // [1,D]
            const float* __restrict__ b_time,   // [D]
            const float* __restrict__ W_static, // [ST,ST]
            const float* __restrict__ b_static, // [ST]
            const float* __restrict__ W_merge,  // [MERGED,MERGED]
            const float* __restrict__ b_merge,  // [MERGED]
            const float* __restrict__ W_cls,    // [MERGED,C]
            const float* __restrict__ b_cls,    // [C]
            float* __restrict__ out)            // [B,C]
{
    const int b    = blockIdx.x;
    const int tid  = threadIdx.x;
    const int lane = tid & 31;

    __shared__ float sx[76];                  // pooled sums; [74]=tsum, [75]=denom
    __shared__ float comb[MERGEDc];
    __shared__ float combr[MERGEDc];
    __shared__ float sens_s[NG][Dc];          // sensor partials
    __shared__ float merge_s[NG][MERGEDc];    // merge partials

    // ---- combine the 4 per-CTA partials from phase1
    if (tid < 76) {
        sx[tid] = (g_part[b][0][tid] + g_part[b][1][tid])
                + (g_part[b][2][tid] + g_part[b][3][tid]);
    }
    __syncthreads();

    const float denomR = sx[Fc + 1];
    const float denomC = fmaxf(denomR, 1e-9f);
    const float tsumR  = sx[Fc];

    // ---- sensor projection partials: 15 f-groups x 64 d-quads (float4)
    if (tid < NG * 64) {
        const int g  = tid >> 6;          // 0..14, f-group
        const int q  = tid & 63;          // d-quad
        const int f0 = g * 5;             // groups 0..13: 5 f, group 14: 4 f
        float4 acc = make_float4(0.f, 0.f, 0.f, 0.f);
#pragma unroll
        for (int k = 0; k < 5; ++k) {
            const int f = f0 + k;
            if (f < Fc) {
                const float  s = sx[f];
                const float4 w = __ldg((const float4*)(W_sensor + f * Dc) + q);
                acc.x += s * w.x; acc.y += s * w.y;
                acc.z += s * w.z; acc.w += s * w.w;
            }
        }
        ((float4*)sens_s[g])[q] = acc;
    } else if (tid >= NG * 64 && tid < NG * 64 + STc) {
        // static embedding (8 threads)
        const int j = tid - NG * 64;
        float a = __ldg(&b_static[j]);
#pragma unroll
        for (int i = 0; i < STc; ++i)
            a += __ldg(&stat_in[b * STc + i]) * __ldg(&W_static[i * STc + j]);
        comb[Dc + j] = a;
    }
    __syncthreads();

    if (tid < Dc) {
        const int d = tid;
        float a = 0.f;
#pragma unroll
        for (int p = 0; p < NG; ++p) a += sens_s[p][d];
        a += tsumR  * __ldg(&W_time[d])
           + denomR * (__ldg(&b_sensor[d]) + __ldg(&b_time[d]));
        comb[d] = a / denomC;
    }
    __syncthreads();

    // ---- merge partials: 15 i-groups x 66 j-quads (float4)
    if (tid < NG * 66) {
        const int g  = tid / 66;          // 0..14, i-group
        const int q  = tid % 66;          // j-quad
        const int i0 = g * 18;            // groups 0..13: 18 i, group 14: 12 i
        const int ni = (g == 14) ? 12 : 18;
        float4 acc = make_float4(0.f, 0.f, 0.f, 0.f);
#pragma unroll 6
        for (int k = 0; k < ni; ++k) {
            const int   i = i0 + k;
            const float c = comb[i];
            const float4 w = __ldg((const float4*)(W_merge + i * MERGEDc) + q);
            acc.x += c * w.x; acc.y += c * w.y;
            acc.z += c * w.z; acc.w += c * w.w;
        }
        ((float4*)merge_s[g])[q] = acc;
    }
    __syncthreads();

    if (tid < MERGEDc) {
        const int j = tid;
        float a = __ldg(&b_merge[j]);
#pragma unroll
        for (int p = 0; p < NG; ++p) a += merge_s[p][j];
        combr[j] = fmaxf(a, 0.f);
    }
    __syncthreads();

    // ---- classifier (warp 0)
    if (tid < 32) {
        float c0 = 0.f, c1 = 0.f;
        for (int i = lane; i < MERGEDc; i += 32) {
            const float v = combr[i];
            c0 += v * __ldg(&W_cls[i * Cc + 0]);
            c1 += v * __ldg(&W_cls[i * Cc + 1]);
        }
#pragma unroll
        for (int o = 16; o > 0; o >>= 1) {
            c0 += __shfl_xor_sync(0xFFFFFFFFu, c0, o);
            c1 += __shfl_xor_sync(0xFFFFFFFFu, c1, o);
        }
        if (lane == 0) {
            out[b * Cc + 0] = c0 + __ldg(&b_cls[0]);
            out[b * Cc + 1] = c1 + __ldg(&b_cls[1]);
        }
    }
}

extern "C" void kernel_launch(void* const* d_in, const int* in_sizes, int n_in,
                              void* d_out, int out_size)
{
    const float* x        = (const float*)d_in[0];
    const float* stat_in  = (const float*)d_in[1];
    const float* time_in  = (const float*)d_in[2];
    const int*   smask    = (const int*)  d_in[3];
    const float* W_sensor = (const float*)d_in[4];
    const float* b_sensor = (const float*)d_in[5];
    const float* W_time   = (const float*)d_in[6];
    const float* b_time   = (const float*)d_in[7];
    const float* W_static = (const float*)d_in[8];
    const float* b_static = (const float*)d_in[9];
    const float* W_merge  = (const float*)d_in[10];
    const float* b_merge  = (const float*)d_in[11];
    const float* W_cls    = (const float*)d_in[12];
    const float* b_cls    = (const float*)d_in[13];
    float* out = (float*)d_out;

    phase1<<<Bc * SPLIT, NT1>>>(x, smask, time_in);
    phase2<<<Bc, NT2>>>(stat_in, W_sensor, b_sensor, W_time, b_time,
                        W_static, b_static, W_merge, b_merge,
                        W_cls, b_cls, out);
}